// round 12
// baseline (speedup 1.0000x reference)
#include <cuda_runtime.h>
#include <cstdint>

// RoIPooling (TF2 crop_and_resize bilinear, POOL=7)
// feature_map: (1, 256, 256, 512) float32 NHWC
// proposals:   (512, 4) int32  [x, y, w, h]
// output:      (512, 7, 7, 512) float32
//
// R8: kernel rides the chip LTS byte cap (~11.9TB/s). Beat it by loading
// fewer L2 bytes STRUCTURALLY (per-load predication regressed twice):
// CTA = (proposal, 64-channel chunk). Phase 1 cp.asyncs the UNIQUE corner
// pixel grid (nrows x ncols <= 14x14) into smem — for small axes the corner
// indices form a contiguous range, so duplicates collapse into one slot by
// construction; the copy loop is unconditional. Phase 2 blends every cell
// from smem (off the L2 path) and streaming-stores. ~7% fewer L2 bytes.

#define POOL   7
#define FM_W   256
#define FM_C   512
#define NPROP  512
#define CHUNK  64                    // channels per CTA
#define NCHUNK (FM_C / CHUNK)        // 8
#define THREADS 256
#define MAXPIX (14 * 14)

__device__ __forceinline__ void cp16(uint32_t dst_smem, const void* src) {
    asm volatile("cp.async.cg.shared.global [%0], [%1], 16;\n"
                 :: "r"(dst_smem), "l"(src) : "memory");
}

// reference-exact axis coords for cell p on an axis of size `size`
__device__ __forceinline__ void axis_coords(int p, int size, float sizef,
                                            int& i0, int& i1, float& fr) {
    float s = ((float)p + 0.5f) * (sizef / (float)POOL) - 0.5f;
    s  = fminf(fmaxf(s, 0.0f), sizef - 1.0f);
    i0 = (int)floorf(s);
    i1 = min(i0 + 1, size - 1);
    fr = s - (float)i0;
}

__global__ __launch_bounds__(THREADS)
void roi_pool_kernel(const float* __restrict__ fm,
                     const int*   __restrict__ props,
                     float*       __restrict__ out)
{
    __shared__ float spix[MAXPIX * CHUNK];          // 49 KB

    const int bid = blockIdx.x;                     // 0 .. 4095
    const int n   = bid >> 3;
    const int ch  = bid & (NCHUNK - 1);
    const int tid = threadIdx.x;

    const int4 box = reinterpret_cast<const int4*>(props)[n];
    const int bx = box.x, by = box.y, bw = box.z, bh = box.w;
    const float wf = (float)bw, hf = (float)bh;

    // axis slot layout:
    //   small axis (size<14): corner indices form contiguous [base, last];
    //     slot = idx - base (dups collapse). count = last - base + 1.
    //   large axis (size>=14): all 14 corners distinct; slot = 2*p + corner.
    const bool ys = (bh < 14), xs = (bw < 14);

    int t0, t1; float tf;
    axis_coords(0, bh, hf, t0, t1, tf);  const int ybase = t0;
    axis_coords(6, bh, hf, t0, t1, tf);  const int nrows = ys ? (t1 - ybase + 1) : 14;
    axis_coords(0, bw, wf, t0, t1, tf);  const int xbase = t0;
    axis_coords(6, bw, wf, t0, t1, tf);  const int ncols = xs ? (t1 - xbase + 1) : 14;

    const int npix = nrows * ncols;

    uint32_t sbase;
    asm("{ .reg .u64 t; cvta.to.shared.u64 t, %1; cvt.u32.u64 %0, t; }"
        : "=r"(sbase) : "l"((const void*)spix));

    // ---- phase 1: stage unique pixel grid (unconditional copy loop) ----
    const float* fmch = fm + ch * CHUNK;
    const int ncp = npix * (CHUNK * 4 / 16);        // 16 cp16 per pixel
    for (int g = tid; g < ncp; g += THREADS) {
        const int p    = g >> 4;
        const int lane = g & 15;
        const int r  = p / ncols;
        const int cc = p - r * ncols;
        // absolute feature-map coords for this slot
        int iy, ix;
        if (ys) { iy = ybase + r; }
        else    { int i0, i1; float fr; axis_coords(r >> 1, bh, hf, i0, i1, fr);
                  iy = (r & 1) ? i1 : i0; }
        if (xs) { ix = xbase + cc; }
        else    { int i0, i1; float fr; axis_coords(cc >> 1, bw, wf, i0, i1, fr);
                  ix = (cc & 1) ? i1 : i0; }
        const float* src = fmch + ((size_t)(by + iy) * FM_W + (bx + ix)) * FM_C + lane * 4;
        cp16(sbase + (uint32_t)(p * (CHUNK * 4) + lane * 16), src);
    }
    asm volatile("cp.async.commit_group;\n" ::: "memory");
    asm volatile("cp.async.wait_group 0;\n" ::: "memory");
    __syncthreads();

    // ---- phase 2: blend all 49 cells from smem ----
    const int ci  = tid & 15;                       // float4 index within chunk
    const int grp = tid >> 4;                       // cell group 0..15
    const float4* P = reinterpret_cast<const float4*>(spix);
    float* obase = out + ((size_t)n * (POOL * POOL)) * FM_C + ch * CHUNK;

    for (int c = grp; c < POOL * POOL; c += 16) {
        const int py = c / POOL;
        const int px = c - py * POOL;

        int iy0, iy1, ix0, ix1; float fy, fx;
        axis_coords(py, bh, hf, iy0, iy1, fy);
        axis_coords(px, bw, wf, ix0, ix1, fx);

        const int s0y = ys ? (iy0 - ybase) : (2 * py);
        const int s1y = ys ? (iy1 - ybase) : (2 * py + 1);
        const int s0x = xs ? (ix0 - xbase) : (2 * px);
        const int s1x = xs ? (ix1 - xbase) : (2 * px + 1);

        const float4 a = P[(s0y * ncols + s0x) * 16 + ci];
        const float4 b = P[(s0y * ncols + s1x) * 16 + ci];
        const float4 g = P[(s1y * ncols + s0x) * 16 + ci];
        const float4 d = P[(s1y * ncols + s1x) * 16 + ci];

        const float ofx = 1.0f - fx;
        const float ofy = 1.0f - fy;

        float4 o;
        o.x = (a.x * ofx + b.x * fx) * ofy + (g.x * ofx + d.x * fx) * fy;
        o.y = (a.y * ofx + b.y * fx) * ofy + (g.y * ofx + d.y * fx) * fy;
        o.z = (a.z * ofx + b.z * fx) * ofy + (g.z * ofx + d.z * fx) * fy;
        o.w = (a.w * ofx + b.w * fx) * ofy + (g.w * ofx + d.w * fx) * fy;

        __stcs(reinterpret_cast<float4*>(obase + (size_t)c * FM_C) + ci, o);
    }
}

extern "C" void kernel_launch(void* const* d_in, const int* in_sizes, int n_in,
                              void* d_out, int out_size)
{
    const float* fm    = (const float*)d_in[0];
    const int*   props = (const int*)d_in[1];
    float*       out   = (float*)d_out;

    const int blocks = NPROP * NCHUNK;    // 4096
    roi_pool_kernel<<<blocks, THREADS>>>(fm, props, out);
}

// round 13
// speedup vs baseline: 1.1623x; 1.1623x over previous
#include <cuda_runtime.h>
#include <cstdint>

// RoIPooling (TF2 crop_and_resize bilinear, POOL=7)
// feature_map: (1, 256, 256, 512) float32 NHWC
// proposals:   (512, 4) int32  [x, y, w, h]
// output:      (512, 7, 7, 512) float32
//
// R9: = R6 (cp.async depth-4 pipeline, barrier-free thread-private smem
// staging, rides the chip LTS byte cap at ~11.9TB/s) with ONE change:
// cp.async.cg -> cp.async.ca. Within a CTA, boxes with w<14 / h<14 reload
// the same corner pixel in consecutive cells (ix1(px)==ix0(px+1), or whole
// duplicate rows). With .cg those duplicates bypass L1 and burn LTS
// bandwidth (the binding cap); with .ca they hit in L1tex and never reach
// L2. Zero instruction-count change — immune to the R4/R7/R8 elision trap.

#define POOL 7
#define FM_W 256
#define FM_C 512
#define NPROP 512
#define C4 (FM_C / 4)
#define DEPTH 4

__device__ __forceinline__ void cp16(uint32_t dst_smem, const void* src) {
    asm volatile("cp.async.ca.shared.global [%0], [%1], 16;\n"
                 :: "r"(dst_smem), "l"(src) : "memory");
}
__device__ __forceinline__ void cp_commit() {
    asm volatile("cp.async.commit_group;\n" ::: "memory");
}
template <int N>
__device__ __forceinline__ void cp_wait() {
    asm volatile("cp.async.wait_group %0;\n" :: "n"(N) : "memory");
}

struct Ctx {
    const float4* row0;
    const float4* row1;
    float4*       orow;
    float wf, xscale, fy, ofy;
    int   bw, c;
    uint32_t sbase;   // smem base address (bytes)
};

// x coords for cell px (bit-identical to reference float32 math)
__device__ __forceinline__ void xcoords(const Ctx& k, int px,
                                        int& ix0, int& ix1, float& fx) {
    float sx = ((float)px + 0.5f) * k.xscale - 0.5f;
    sx = fminf(fmaxf(sx, 0.0f), k.wf - 1.0f);
    ix0 = (int)floorf(sx);
    ix1 = min(ix0 + 1, k.bw - 1);
    fx  = sx - (float)ix0;
}

// stage slot layout: slot s, corner j, thread t at sbase + ((s*4+j)*128 + t)*16
__device__ __forceinline__ uint32_t slot_addr(const Ctx& k, int s, int j) {
    return k.sbase + (uint32_t)(((s * 4 + j) * 128 + k.c) * 16);
}

__device__ __forceinline__ void issue(const Ctx& k, int px) {
    int ix0, ix1; float fx;
    xcoords(k, px, ix0, ix1, fx);
    const int s = px & (DEPTH - 1);
    cp16(slot_addr(k, s, 0), &k.row0[ix0 * C4 + k.c]);
    cp16(slot_addr(k, s, 1), &k.row0[ix1 * C4 + k.c]);
    cp16(slot_addr(k, s, 2), &k.row1[ix0 * C4 + k.c]);
    cp16(slot_addr(k, s, 3), &k.row1[ix1 * C4 + k.c]);
    cp_commit();
}

template <int WC>
__device__ __forceinline__ void consume(const Ctx& k, const float4* buf, int px) {
    int ix0, ix1; float fx;
    xcoords(k, px, ix0, ix1, fx);          // recompute (cheap ALU, saves regs)
    const float of = 1.0f - fx;
    const int s = px & (DEPTH - 1);

    cp_wait<WC>();                          // stage px's group retired

    const float4 a = buf[(s * 4 + 0) * 128 + k.c];
    const float4 b = buf[(s * 4 + 1) * 128 + k.c];
    const float4 g = buf[(s * 4 + 2) * 128 + k.c];
    const float4 d = buf[(s * 4 + 3) * 128 + k.c];

    float4 o;
    o.x = (a.x * of + b.x * fx) * k.ofy + (g.x * of + d.x * fx) * k.fy;
    o.y = (a.y * of + b.y * fx) * k.ofy + (g.y * of + d.y * fx) * k.fy;
    o.z = (a.z * of + b.z * fx) * k.ofy + (g.z * of + d.z * fx) * k.fy;
    o.w = (a.w * of + b.w * fx) * k.ofy + (g.w * of + d.w * fx) * k.fy;

    __stcs(&k.orow[px * C4 + k.c], o);
}

__global__ __launch_bounds__(128)
void roi_pool_kernel(const float* __restrict__ fm,
                     const int*   __restrict__ props,
                     float*       __restrict__ out)
{
    __shared__ float4 buf[DEPTH * 4 * 128];    // 32 KB

    const int bid = blockIdx.x;                // 0 .. 3583
    const int n   = bid / POOL;
    const int py  = bid - n * POOL;

    const int4 box = reinterpret_cast<const int4*>(props)[n];
    const int bx = box.x, by = box.y, bw = box.z, bh = box.w;

    // --- y axis coords ---
    const float hf = (float)bh;
    float sy = ((float)py + 0.5f) * (hf / (float)POOL) - 0.5f;
    sy = fminf(fmaxf(sy, 0.0f), hf - 1.0f);
    const int   iy0 = (int)floorf(sy);
    const int   iy1 = min(iy0 + 1, bh - 1);

    Ctx k;
    k.fy  = sy - (float)iy0;
    k.ofy = 1.0f - k.fy;
    k.row0 = reinterpret_cast<const float4*>(fm + ((size_t)(by + iy0) * FM_W + bx) * FM_C);
    k.row1 = reinterpret_cast<const float4*>(fm + ((size_t)(by + iy1) * FM_W + bx) * FM_C);
    k.orow = reinterpret_cast<float4*>(out + ((size_t)n * (POOL * POOL) + (size_t)py * POOL) * FM_C);
    k.c   = threadIdx.x;
    k.bw  = bw;
    k.wf  = (float)bw;
    k.xscale = k.wf / (float)POOL;
    {
        uint32_t a;
        asm("{ .reg .u64 t; cvta.to.shared.u64 t, %1; cvt.u32.u64 %0, t; }"
            : "=r"(a) : "l"((const void*)buf));
        k.sbase = a;
    }

    // prologue: fill the pipe (4 stages in flight)
    issue(k, 0); issue(k, 1); issue(k, 2); issue(k, 3);

    // steady state + drain; wait counts keep exactly stage-px retired
    consume<3>(k, buf, 0); issue(k, 4);
    consume<3>(k, buf, 1); issue(k, 5);
    consume<3>(k, buf, 2); issue(k, 6);
    consume<3>(k, buf, 3);
    consume<2>(k, buf, 4);
    consume<1>(k, buf, 5);
    consume<0>(k, buf, 6);
}

extern "C" void kernel_launch(void* const* d_in, const int* in_sizes, int n_in,
                              void* d_out, int out_size)
{
    const float* fm    = (const float*)d_in[0];
    const int*   props = (const int*)d_in[1];
    float*       out   = (float*)d_out;

    const int blocks = NPROP * POOL;      // 3584
    roi_pool_kernel<<<blocks, 128>>>(fm, props, out);
}

// round 14
// speedup vs baseline: 2.1566x; 1.8554x over previous
#include <cuda_runtime.h>
#include <cstdint>

// RoIPooling (TF2 crop_and_resize bilinear, POOL=7)
// feature_map: (1, 256, 256, 512) float32 NHWC
// proposals:   (512, 4) int32  [x, y, w, h]
// output:      (512, 7, 7, 512) float32
//
// R10: = R6 (cp.async.cg depth-4 pipeline, barrier-free thread-private smem
// staging; rides the chip LTS byte cap ~11.9TB/s = 21.5us) + ONE per-CTA-
// uniform elision: when row1 contributes nothing distinct (fy==0 for all
// cells of this proposal, or iy1==iy0 clamp), skip its two cp.asyncs.
// Consumer remap is two loop-invariant slot indices (jg,jd) in Ctx — the
// per-px hot path is instruction-identical to R6. Substitution g:=a, d:=b
// is bit-exact (same pixel, or weight exactly 0.0).
// Lessons encoded: per-px predication (R4/R7), per-copy address machinery
// (R8), and L1 re-routing (R9) all regressed; .cg bypass is load-bearing.

#define POOL 7
#define FM_W 256
#define FM_C 512
#define NPROP 512
#define C4 (FM_C / 4)
#define DEPTH 4

__device__ __forceinline__ void cp16(uint32_t dst_smem, const void* src) {
    asm volatile("cp.async.cg.shared.global [%0], [%1], 16;\n"
                 :: "r"(dst_smem), "l"(src) : "memory");
}
__device__ __forceinline__ void cp_commit() {
    asm volatile("cp.async.commit_group;\n" ::: "memory");
}
template <int N>
__device__ __forceinline__ void cp_wait() {
    asm volatile("cp.async.wait_group %0;\n" :: "n"(N) : "memory");
}

struct Ctx {
    const float4* row0;
    const float4* row1;
    float4*       orow;
    float wf, xscale, fy, ofy;
    int   bw, c;
    int   jg, jd;      // consumer slot indices for corners g,d (loop-invariant)
    bool  need_y1;     // row1 contributes distinct bytes
    uint32_t sbase;    // smem base address (bytes)
};

// x coords for cell px (bit-identical to reference float32 math)
__device__ __forceinline__ void xcoords(const Ctx& k, int px,
                                        int& ix0, int& ix1, float& fx) {
    float sx = ((float)px + 0.5f) * k.xscale - 0.5f;
    sx = fminf(fmaxf(sx, 0.0f), k.wf - 1.0f);
    ix0 = (int)floorf(sx);
    ix1 = min(ix0 + 1, k.bw - 1);
    fx  = sx - (float)ix0;
}

// stage slot layout: slot s, corner j, thread t at sbase + ((s*4+j)*128 + t)*16
__device__ __forceinline__ uint32_t slot_addr(const Ctx& k, int s, int j) {
    return k.sbase + (uint32_t)(((s * 4 + j) * 128 + k.c) * 16);
}

__device__ __forceinline__ void issue(const Ctx& k, int px) {
    int ix0, ix1; float fx;
    xcoords(k, px, ix0, ix1, fx);
    const int s = px & (DEPTH - 1);
    cp16(slot_addr(k, s, 0), &k.row0[ix0 * C4 + k.c]);
    cp16(slot_addr(k, s, 1), &k.row0[ix1 * C4 + k.c]);
    if (k.need_y1) {   // CTA-uniform: one predictable branch, no data chain
        cp16(slot_addr(k, s, 2), &k.row1[ix0 * C4 + k.c]);
        cp16(slot_addr(k, s, 3), &k.row1[ix1 * C4 + k.c]);
    }
    cp_commit();
}

template <int WC>
__device__ __forceinline__ void consume(const Ctx& k, const float4* buf, int px) {
    int ix0, ix1; float fx;
    xcoords(k, px, ix0, ix1, fx);          // recompute (cheap ALU, saves regs)
    const float of = 1.0f - fx;
    const int s = px & (DEPTH - 1);

    cp_wait<WC>();                          // stage px's group retired

    const float4 a = buf[(s * 4 + 0)    * 128 + k.c];
    const float4 b = buf[(s * 4 + 1)    * 128 + k.c];
    const float4 g = buf[(s * 4 + k.jg) * 128 + k.c];
    const float4 d = buf[(s * 4 + k.jd) * 128 + k.c];

    float4 o;
    o.x = (a.x * of + b.x * fx) * k.ofy + (g.x * of + d.x * fx) * k.fy;
    o.y = (a.y * of + b.y * fx) * k.ofy + (g.y * of + d.y * fx) * k.fy;
    o.z = (a.z * of + b.z * fx) * k.ofy + (g.z * of + d.z * fx) * k.fy;
    o.w = (a.w * of + b.w * fx) * k.ofy + (g.w * of + d.w * fx) * k.fy;

    __stcs(&k.orow[px * C4 + k.c], o);
}

__global__ __launch_bounds__(128)
void roi_pool_kernel(const float* __restrict__ fm,
                     const int*   __restrict__ props,
                     float*       __restrict__ out)
{
    __shared__ float4 buf[DEPTH * 4 * 128];    // 32 KB

    const int bid = blockIdx.x;                // 0 .. 3583
    const int n   = bid / POOL;
    const int py  = bid - n * POOL;

    const int4 box = reinterpret_cast<const int4*>(props)[n];
    const int bx = box.x, by = box.y, bw = box.z, bh = box.w;

    // --- y axis coords ---
    const float hf = (float)bh;
    float sy = ((float)py + 0.5f) * (hf / (float)POOL) - 0.5f;
    sy = fminf(fmaxf(sy, 0.0f), hf - 1.0f);
    const int   iy0 = (int)floorf(sy);
    const int   iy1 = min(iy0 + 1, bh - 1);

    Ctx k;
    k.fy  = sy - (float)iy0;
    k.ofy = 1.0f - k.fy;
    k.need_y1 = (iy1 != iy0) && (k.fy != 0.0f);
    k.jg = k.need_y1 ? 2 : 0;   // !need_y1: g := a (clamp dup / zero weight)
    k.jd = k.need_y1 ? 3 : 1;   // !need_y1: d := b
    k.row0 = reinterpret_cast<const float4*>(fm + ((size_t)(by + iy0) * FM_W + bx) * FM_C);
    k.row1 = reinterpret_cast<const float4*>(fm + ((size_t)(by + iy1) * FM_W + bx) * FM_C);
    k.orow = reinterpret_cast<float4*>(out + ((size_t)n * (POOL * POOL) + (size_t)py * POOL) * FM_C);
    k.c   = threadIdx.x;
    k.bw  = bw;
    k.wf  = (float)bw;
    k.xscale = k.wf / (float)POOL;
    {
        uint32_t a;
        asm("{ .reg .u64 t; cvta.to.shared.u64 t, %1; cvt.u32.u64 %0, t; }"
            : "=r"(a) : "l"((const void*)buf));
        k.sbase = a;
    }

    // prologue: fill the pipe (4 stages in flight)
    issue(k, 0); issue(k, 1); issue(k, 2); issue(k, 3);

    // steady state + drain; wait counts keep exactly stage-px retired
    consume<3>(k, buf, 0); issue(k, 4);
    consume<3>(k, buf, 1); issue(k, 5);
    consume<3>(k, buf, 2); issue(k, 6);
    consume<3>(k, buf, 3);
    consume<2>(k, buf, 4);
    consume<1>(k, buf, 5);
    consume<0>(k, buf, 6);
}

extern "C" void kernel_launch(void* const* d_in, const int* in_sizes, int n_in,
                              void* d_out, int out_size)
{
    const float* fm    = (const float*)d_in[0];
    const int*   props = (const int*)d_in[1];
    float*       out   = (float*)d_out;

    const int blocks = NPROP * POOL;      // 3584
    roi_pool_kernel<<<blocks, 128>>>(fm, props, out);
}

// round 15
// speedup vs baseline: 2.1863x; 1.0137x over previous
#include <cuda_runtime.h>
#include <cstdint>

// RoIPooling (TF2 crop_and_resize bilinear, POOL=7)
// feature_map: (1, 256, 256, 512) float32 NHWC
// proposals:   (512, 4) int32  [x, y, w, h]
// output:      (512, 7, 7, 512) float32
//
// R11: = R10 (cp.async.cg depth-4 pipeline + CTA-uniform y-elision, 21.25us)
// + the symmetric CTA-uniform x-elision: if NO px cell of this proposal
// needs the x1 column (fx==0 or ix1==ix0 for all 7 px — w ≡ 7 mod 14 or
// clamp collapse, ~9% of boxes), skip corners 1,3 in issue(). The flag is
// computed once at setup; the consumer remap is loop-invariant slot indices
// (jb,jg,jd) in Ctx. Per-px hot path instruction-identical to R6/R10 — the
// only elision shape that has worked (per-px predication, per-copy address
// machinery, and L1 rerouting all regressed).

#define POOL 7
#define FM_W 256
#define FM_C 512
#define NPROP 512
#define C4 (FM_C / 4)
#define DEPTH 4

__device__ __forceinline__ void cp16(uint32_t dst_smem, const void* src) {
    asm volatile("cp.async.cg.shared.global [%0], [%1], 16;\n"
                 :: "r"(dst_smem), "l"(src) : "memory");
}
__device__ __forceinline__ void cp_commit() {
    asm volatile("cp.async.commit_group;\n" ::: "memory");
}
template <int N>
__device__ __forceinline__ void cp_wait() {
    asm volatile("cp.async.wait_group %0;\n" :: "n"(N) : "memory");
}

struct Ctx {
    const float4* row0;
    const float4* row1;
    float4*       orow;
    float wf, xscale, fy, ofy;
    int   bw, c;
    int   jb, jg, jd;  // consumer slot indices for corners b,g,d (loop-invariant)
    bool  need_y1;     // row1 contributes distinct bytes
    bool  need_x1;     // some px needs the x1 column
    uint32_t sbase;    // smem base address (bytes)
};

// x coords for cell px (bit-identical to reference float32 math)
__device__ __forceinline__ void xcoords(const Ctx& k, int px,
                                        int& ix0, int& ix1, float& fx) {
    float sx = ((float)px + 0.5f) * k.xscale - 0.5f;
    sx = fminf(fmaxf(sx, 0.0f), k.wf - 1.0f);
    ix0 = (int)floorf(sx);
    ix1 = min(ix0 + 1, k.bw - 1);
    fx  = sx - (float)ix0;
}

// stage slot layout: slot s, corner j, thread t at sbase + ((s*4+j)*128 + t)*16
__device__ __forceinline__ uint32_t slot_addr(const Ctx& k, int s, int j) {
    return k.sbase + (uint32_t)(((s * 4 + j) * 128 + k.c) * 16);
}

__device__ __forceinline__ void issue(const Ctx& k, int px) {
    int ix0, ix1; float fx;
    xcoords(k, px, ix0, ix1, fx);
    const int s = px & (DEPTH - 1);
    cp16(slot_addr(k, s, 0), &k.row0[ix0 * C4 + k.c]);
    if (k.need_x1)                cp16(slot_addr(k, s, 1), &k.row0[ix1 * C4 + k.c]);
    if (k.need_y1)                cp16(slot_addr(k, s, 2), &k.row1[ix0 * C4 + k.c]);
    if (k.need_x1 && k.need_y1)   cp16(slot_addr(k, s, 3), &k.row1[ix1 * C4 + k.c]);
    cp_commit();
}

template <int WC>
__device__ __forceinline__ void consume(const Ctx& k, const float4* buf, int px) {
    int ix0, ix1; float fx;
    xcoords(k, px, ix0, ix1, fx);          // recompute (cheap ALU, saves regs)
    const float of = 1.0f - fx;
    const int s = px & (DEPTH - 1);

    cp_wait<WC>();                          // stage px's group retired

    const float4 a = buf[(s * 4 + 0)    * 128 + k.c];
    const float4 b = buf[(s * 4 + k.jb) * 128 + k.c];
    const float4 g = buf[(s * 4 + k.jg) * 128 + k.c];
    const float4 d = buf[(s * 4 + k.jd) * 128 + k.c];

    float4 o;
    o.x = (a.x * of + b.x * fx) * k.ofy + (g.x * of + d.x * fx) * k.fy;
    o.y = (a.y * of + b.y * fx) * k.ofy + (g.y * of + d.y * fx) * k.fy;
    o.z = (a.z * of + b.z * fx) * k.ofy + (g.z * of + d.z * fx) * k.fy;
    o.w = (a.w * of + b.w * fx) * k.ofy + (g.w * of + d.w * fx) * k.fy;

    __stcs(&k.orow[px * C4 + k.c], o);
}

__global__ __launch_bounds__(128)
void roi_pool_kernel(const float* __restrict__ fm,
                     const int*   __restrict__ props,
                     float*       __restrict__ out)
{
    __shared__ float4 buf[DEPTH * 4 * 128];    // 32 KB

    const int bid = blockIdx.x;                // 0 .. 3583
    const int n   = bid / POOL;
    const int py  = bid - n * POOL;

    const int4 box = reinterpret_cast<const int4*>(props)[n];
    const int bx = box.x, by = box.y, bw = box.z, bh = box.w;

    // --- y axis coords ---
    const float hf = (float)bh;
    float sy = ((float)py + 0.5f) * (hf / (float)POOL) - 0.5f;
    sy = fminf(fmaxf(sy, 0.0f), hf - 1.0f);
    const int   iy0 = (int)floorf(sy);
    const int   iy1 = min(iy0 + 1, bh - 1);

    Ctx k;
    k.fy  = sy - (float)iy0;
    k.ofy = 1.0f - k.fy;
    k.need_y1 = (iy1 != iy0) && (k.fy != 0.0f);
    k.row0 = reinterpret_cast<const float4*>(fm + ((size_t)(by + iy0) * FM_W + bx) * FM_C);
    k.row1 = reinterpret_cast<const float4*>(fm + ((size_t)(by + iy1) * FM_W + bx) * FM_C);
    k.orow = reinterpret_cast<float4*>(out + ((size_t)n * (POOL * POOL) + (size_t)py * POOL) * FM_C);
    k.c   = threadIdx.x;
    k.bw  = bw;
    k.wf  = (float)bw;
    k.xscale = k.wf / (float)POOL;

    // CTA-uniform x flag: does ANY px cell need the x1 column?
    {
        bool nx = false;
        #pragma unroll
        for (int px = 0; px < POOL; ++px) {
            int i0, i1; float fr;
            xcoords(k, px, i0, i1, fr);
            nx |= ((i1 != i0) && (fr != 0.0f));
        }
        k.need_x1 = nx;
    }
    k.jb = k.need_x1 ? 1 : 0;                              // !need_x1: b := a
    k.jg = k.need_y1 ? 2 : 0;                              // !need_y1: g := a
    k.jd = k.need_y1 ? (k.need_x1 ? 3 : 2) : k.jb;         // d := b/g/a as appropriate
    {
        uint32_t a;
        asm("{ .reg .u64 t; cvta.to.shared.u64 t, %1; cvt.u32.u64 %0, t; }"
            : "=r"(a) : "l"((const void*)buf));
        k.sbase = a;
    }

    // prologue: fill the pipe (4 stages in flight)
    issue(k, 0); issue(k, 1); issue(k, 2); issue(k, 3);

    // steady state + drain; wait counts keep exactly stage-px retired
    consume<3>(k, buf, 0); issue(k, 4);
    consume<3>(k, buf, 1); issue(k, 5);
    consume<3>(k, buf, 2); issue(k, 6);
    consume<3>(k, buf, 3);
    consume<2>(k, buf, 4);
    consume<1>(k, buf, 5);
    consume<0>(k, buf, 6);
}

extern "C" void kernel_launch(void* const* d_in, const int* in_sizes, int n_in,
                              void* d_out, int out_size)
{
    const float* fm    = (const float*)d_in[0];
    const int*   props = (const int*)d_in[1];
    float*       out   = (float*)d_out;

    const int blocks = NPROP * POOL;      // 3584
    roi_pool_kernel<<<blocks, 128>>>(fm, props, out);
}